// round 14
// baseline (speedup 1.0000x reference)
#include <cuda_runtime.h>
#include <cuda_bf16.h>
#include <cstdint>

// Problem constants (from reference)
#define OUTF    11008
#define INF     4096
#define NGROUPS 32      // INF / 128
#define GSIZE   128
#define BATCH   8

#define THREADS 128
#define WARPS   4
#define NOUT    2                       // output rows per warp
#define OUT_PER_BLOCK (WARPS * NOUT)    // 8
#define GRID    (OUTF / OUT_PER_BLOCK)  // 1376
#define STAGES  4                       // cp.async pipeline depth (4 KB/stage)

typedef unsigned long long ull;

// ---- packed f32x2 helpers (Blackwell FFMA2; PTX-only) ----
__device__ __forceinline__ ull pack2(uint32_t lo, uint32_t hi) {
    ull r; asm("mov.b64 %0, {%1, %2};" : "=l"(r) : "r"(lo), "r"(hi)); return r;
}
__device__ __forceinline__ ull ffma2(ull a, ull b, ull c) {
    ull d; asm("fma.rn.f32x2 %0, %1, %2, %3;" : "=l"(d) : "l"(a), "l"(b), "l"(c)); return d;
}
__device__ __forceinline__ void unpack2(ull v, float& lo, float& hi) {
    asm("mov.b64 {%0, %1}, %2;" : "=f"(lo), "=f"(hi) : "l"(v));
}
__device__ __forceinline__ float bf16_rn(float v) {
    return __bfloat162float(__float2bfloat16_rn(v));
}

// 64 KB scratch: x transposed/packed. Entry i = (g*4+j)*32 + lane holds
// all 8 batches (bf16) of x at k = g*128 + lane*4 + j.
__device__ __align__(16) uint4 g_xt[INF];

__global__ void xt_kernel(const float* __restrict__ x) {
    const int i = blockIdx.x * blockDim.x + threadIdx.x;   // 0..4095
    if (i >= INF) return;
    const int lane = i & 31;
    const int gj   = i >> 5;
    const int g    = gj >> 2;
    const int j    = gj & 3;
    const int k    = g * GSIZE + lane * 4 + j;
    uint32_t u[4];
    #pragma unroll
    for (int bp = 0; bp < 4; bp++) {
        const float f0 = x[(size_t)(2 * bp) * INF + k];
        const float f1 = x[(size_t)(2 * bp + 1) * INF + k];
        __nv_bfloat162 p = __floats2bfloat162_rn(f0, f1);   // exact: values are bf16-valued
        u[bp] = *reinterpret_cast<uint32_t*>(&p);           // {b_even lo16, b_odd hi16}
    }
    g_xt[i] = make_uint4(u[0], u[1], u[2], u[3]);
}

__device__ __forceinline__ void cp_async16(void* smem_dst, const void* gmem_src) {
    const uint32_t d = (uint32_t)__cvta_generic_to_shared(smem_dst);
    asm volatile("cp.async.cg.shared.global [%0], [%1], 16;" :: "r"(d), "l"(gmem_src));
}
__device__ __forceinline__ void cp_commit() {
    asm volatile("cp.async.commit_group;");
}

__global__ __launch_bounds__(THREADS, 8)
void wo4l_kernel(const int* __restrict__ qw,       // int32 codes 0..15, [11008][4096]
                 const float2* __restrict__ sz,    // f32 {scale, zero}, [32][11008]
                 float* __restrict__ out)          // f32 (bf16-valued), [8][11008]
{
    // q staging: per stage, 8 rows x 128 codes = 4 KB; 4 stages = 16 KB
    __shared__ __align__(16) int4 sq[STAGES][OUT_PER_BLOCK * 32];

    const int tid    = threadIdx.x;
    const int warp   = tid >> 5;
    const int lane   = tid & 31;
    const int oblock = blockIdx.x * OUT_PER_BLOCK;
    const int o0     = oblock + warp * NOUT;

    const int4* qp = (const int4*)qw;   // 4 codes per 16B

    // ---- prologue: stage groups 0..STAGES-2 (2 cp.async per thread each) ----
    #pragma unroll
    for (int st = 0; st < STAGES - 1; st++) {
        #pragma unroll
        for (int i = 0; i < 2; i++) {
            const int c = tid + i * THREADS;         // 0..255
            const int row = c >> 5, col = c & 31;
            cp_async16(&sq[st][c], &qp[(size_t)(oblock + row) * (INF / 4) + st * 32 + col]);
        }
        cp_commit();
    }

    ull acc[NOUT][4];                   // [row][batch-pair] packed f32x2
    #pragma unroll
    for (int n = 0; n < NOUT; n++)
        #pragma unroll
        for (int bp = 0; bp < 4; bp++)
            acc[n][bp] = 0ull;

    for (int g = 0; g < NGROUPS; ++g) {
        // group g's tile is complete when <= STAGES-2 commit-groups pend
        asm volatile("cp.async.wait_group %0;" :: "n"(STAGES - 2));
        __syncthreads();   // publish stage; fences prior-stage reads

        // refill: group g+STAGES-1 into its stage
        const int gn = g + STAGES - 1;
        if (gn < NGROUPS) {
            const int st = gn & (STAGES - 1);
            #pragma unroll
            for (int i = 0; i < 2; i++) {
                const int c = tid + i * THREADS;
                const int row = c >> 5, col = c & 31;
                cp_async16(&sq[st][c], &qp[(size_t)(oblock + row) * (INF / 4) + gn * 32 + col]);
            }
        }
        cp_commit();       // uniform commits keep group counts aligned in the tail

        // per-group scale/zero (uniform across lanes)
        float s[NOUT], m8s[NOUT];
        __nv_bfloat162 z2[NOUT];
        #pragma unroll
        for (int n = 0; n < NOUT; n++) {
            const float2 v = __ldg(&sz[(size_t)g * OUTF + o0 + n]);
            s[n]   = v.x;
            m8s[n] = -8.0f * v.x;                                    // exact
            z2[n]  = __bfloat162bfloat162(__float2bfloat16_rn(v.y)); // {z,z}
        }

        // q codes from smem (single LDS.128 per row)
        const int st = g & (STAGES - 1);
        int4 qv[NOUT];
        #pragma unroll
        for (int n = 0; n < NOUT; n++)
            qv[n] = sq[st][(warp * NOUT + n) * 32 + lane];

        // k-pairs: jp=0 -> (j0,j1)=(0,1), jp=1 -> (2,3)
        #pragma unroll
        for (int jp = 0; jp < 2; ++jp) {
            // x for the two k's: one LDG.128 each = all 8 batches (bf16-packed)
            const uint4 xa = __ldg(&g_xt[(g * 4 + 2 * jp)     * 32 + lane]);
            const uint4 xb = __ldg(&g_xt[(g * 4 + 2 * jp + 1) * 32 + lane]);
            ull x2a[4], x2b[4];
            {
                const uint32_t ua[4] = {xa.x, xa.y, xa.z, xa.w};
                const uint32_t ub[4] = {xb.x, xb.y, xb.z, xb.w};
                #pragma unroll
                for (int bp = 0; bp < 4; bp++) {
                    x2a[bp] = pack2(ua[bp] << 16, ua[bp] & 0xffff0000u);
                    x2b[bp] = pack2(ub[bp] << 16, ub[bp] & 0xffff0000u);
                }
            }
            #pragma unroll
            for (int n = 0; n < NOUT; n++) {
                const int qa = jp ? qv[n].z : qv[n].x;
                const int qb = jp ? qv[n].w : qv[n].y;
                // exact (q-8)*s in f32, RN->bf16 (ref bf16 mul), bf16 add of zero
                const float ta = fmaf((float)qa, s[n], m8s[n]);
                const float tb = fmaf((float)qb, s[n], m8s[n]);
                const __nv_bfloat162 w2 = __hadd2(__floats2bfloat162_rn(ta, tb), z2[n]);
                const uint32_t w2u = *reinterpret_cast<const uint32_t*>(&w2);
                const uint32_t wau = w2u << 16;
                const uint32_t wbu = w2u & 0xffff0000u;
                const ull wa2 = pack2(wau, wau);
                const ull wb2 = pack2(wbu, wbu);
                #pragma unroll
                for (int bp = 0; bp < 4; bp++) {
                    acc[n][bp] = ffma2(wa2, x2a[bp], acc[n][bp]);
                    acc[n][bp] = ffma2(wb2, x2b[bp], acc[n][bp]);
                }
            }
        }
    }

    // unpack and warp-reduce
    float r[NOUT][BATCH];
    #pragma unroll
    for (int n = 0; n < NOUT; n++)
        #pragma unroll
        for (int bp = 0; bp < 4; bp++)
            unpack2(acc[n][bp], r[n][2 * bp], r[n][2 * bp + 1]);

    #pragma unroll
    for (int m = 16; m >= 1; m >>= 1)
        #pragma unroll
        for (int n = 0; n < NOUT; n++)
            #pragma unroll
            for (int b = 0; b < BATCH; b++)
                r[n][b] += __shfl_xor_sync(0xffffffffu, r[n][b], m);

    // epilogue: lane b stores batch b; bf16-round (ref output is bf16-valued)
    #pragma unroll
    for (int b = 0; b < BATCH; b++) {
        if (lane == b) {
            #pragma unroll
            for (int n = 0; n < NOUT; n++)
                out[(size_t)b * OUTF + o0 + n] = bf16_rn(r[n][b]);
        }
    }
}

extern "C" void kernel_launch(void* const* d_in, const int* in_sizes, int n_in,
                              void* d_out, int out_size)
{
    // Route inputs by element count (order-proof); fall back to positional.
    const float*  x  = nullptr;   // 8*4096      = 32768
    const int*    qw = nullptr;   // 11008*4096  = 45088768
    const float2* sz = nullptr;   // 32*11008*2  = 704512 scalars
    for (int i = 0; i < n_in; i++) {
        if      (in_sizes[i] == BATCH * INF)         x  = (const float*)d_in[i];
        else if (in_sizes[i] == OUTF * INF)          qw = (const int*)d_in[i];
        else if (in_sizes[i] == NGROUPS * OUTF * 2)  sz = (const float2*)d_in[i];
    }
    if (!x || !qw || !sz) {
        x  = (const float*)d_in[0];
        qw = (const int*)d_in[1];
        sz = (const float2*)d_in[2];
    }
    float* out = (float*)d_out;

    xt_kernel<<<INF / 128, 128>>>(x);
    wo4l_kernel<<<GRID, THREADS>>>(qw, sz, out);
}

// round 15
// speedup vs baseline: 1.2893x; 1.2893x over previous
#include <cuda_runtime.h>
#include <cuda_bf16.h>
#include <cstdint>

// Problem constants (from reference)
#define OUTF    11008
#define INF     4096
#define NGROUPS 32      // INF / 128
#define GSIZE   128
#define BATCH   8

#define THREADS 128
#define WARPS   4
#define NOUT    4                       // output rows per warp
#define OUT_PER_BLOCK (WARPS * NOUT)    // 16
#define GRID    (OUTF / OUT_PER_BLOCK)  // 344

typedef unsigned long long ull;

// ---- packed f32x2 helpers (Blackwell FFMA2; PTX-only) ----
__device__ __forceinline__ ull pack2(uint32_t lo, uint32_t hi) {
    ull r; asm("mov.b64 %0, {%1, %2};" : "=l"(r) : "r"(lo), "r"(hi)); return r;
}
__device__ __forceinline__ ull ffma2(ull a, ull b, ull c) {
    ull d; asm("fma.rn.f32x2 %0, %1, %2, %3;" : "=l"(d) : "l"(a), "l"(b), "l"(c)); return d;
}
__device__ __forceinline__ void unpack2(ull v, float& lo, float& hi) {
    asm("mov.b64 {%0, %1}, %2;" : "=f"(lo), "=f"(hi) : "l"(v));
}
__device__ __forceinline__ float bf16_rn(float v) {
    return __bfloat162float(__float2bfloat16_rn(v));
}

// 64 KB scratch: x transposed/packed. Entry i = (g*4+j)*32 + lane holds
// all 8 batches (bf16) of x at k = g*128 + lane*4 + j.
__device__ __align__(16) uint4 g_xt[INF];

// thread t <-> k = t. Coalesced reads of x; scattered 16B writes (absorbed by L2).
__global__ __launch_bounds__(256)
void xt_kernel(const float* __restrict__ x) {
    const int k = blockIdx.x * 256 + threadIdx.x;   // 0..4095
    const int g    = k >> 7;
    const int r    = k & 127;
    const int lane = r >> 2;
    const int j    = r & 3;
    uint32_t u[4];
    #pragma unroll
    for (int bp = 0; bp < 4; bp++) {
        const float f0 = x[(size_t)(2 * bp) * INF + k];
        const float f1 = x[(size_t)(2 * bp + 1) * INF + k];
        __nv_bfloat162 p = __floats2bfloat162_rn(f0, f1);   // exact: values are bf16-valued
        u[bp] = *reinterpret_cast<uint32_t*>(&p);           // {b_even lo16, b_odd hi16}
    }
    g_xt[(g * 4 + j) * 32 + lane] = make_uint4(u[0], u[1], u[2], u[3]);
}

__global__ __launch_bounds__(THREADS, 5)
void wo4l_kernel(const int* __restrict__ qw,       // int32 codes 0..15, [11008][4096]
                 const float2* __restrict__ sz,    // f32 {scale, zero}, [32][11008]
                 float* __restrict__ out)          // f32 (bf16-valued), [8][11008]
{
    // All scale/zero pairs this block ever needs: [group][row] = 4 KB.
    __shared__ float2 ssz[NGROUPS][OUT_PER_BLOCK];

    const int tid    = threadIdx.x;
    const int warp   = tid >> 5;
    const int lane   = tid & 31;
    const int oblock = blockIdx.x * OUT_PER_BLOCK;
    const int o0     = oblock + warp * NOUT;

    // ---- prologue: stage sz for all 32 groups x 16 rows (coalesced) ----
    #pragma unroll
    for (int i = 0; i < NGROUPS * OUT_PER_BLOCK / THREADS; i++) {
        const int c = tid + i * THREADS;        // 0..511
        const int gg = c >> 4, rr = c & 15;
        ssz[gg][rr] = __ldg(&sz[(size_t)gg * OUTF + oblock + rr]);
    }
    __syncthreads();

    const int4* qp = (const int4*)qw;   // lane's k-slice: g*128 + lane*4 + 0..3

    ull acc[NOUT][4];                   // [row][batch-pair] packed f32x2
    #pragma unroll
    for (int n = 0; n < NOUT; n++)
        #pragma unroll
        for (int bp = 0; bp < 4; bp++)
            acc[n][bp] = 0ull;

    // prefetch group 0's q codes
    int4 qv[NOUT];
    #pragma unroll
    for (int n = 0; n < NOUT; n++)
        qv[n] = __ldcs(&qp[(size_t)(o0 + n) * (INF / 4) + lane]);

    for (int g = 0; g < NGROUPS; ++g) {
        // prefetch next group's q (covers DRAM latency)
        int4 qn[NOUT];
        if (g + 1 < NGROUPS) {
            #pragma unroll
            for (int n = 0; n < NOUT; n++)
                qn[n] = __ldcs(&qp[(size_t)(o0 + n) * (INF / 4) + (g + 1) * 32 + lane]);
        }

        // per-group scale/zero from smem (broadcast LDS, no L2 join)
        float s[NOUT], m8s[NOUT];
        __nv_bfloat162 z2[NOUT];
        #pragma unroll
        for (int n = 0; n < NOUT; n++) {
            const float2 v = ssz[g][warp * NOUT + n];
            s[n]   = v.x;
            m8s[n] = -8.0f * v.x;                                    // exact
            z2[n]  = __bfloat162bfloat162(__float2bfloat16_rn(v.y)); // {z,z}
        }

        // k-pairs: jp=0 -> (j0,j1)=(0,1), jp=1 -> (2,3)
        #pragma unroll
        for (int jp = 0; jp < 2; ++jp) {
            // x for the two k's: one LDG.128 each = all 8 batches (bf16-packed)
            const uint4 xa = __ldg(&g_xt[(g * 4 + 2 * jp)     * 32 + lane]);
            const uint4 xb = __ldg(&g_xt[(g * 4 + 2 * jp + 1) * 32 + lane]);
            ull x2a[4], x2b[4];
            {
                const uint32_t ua[4] = {xa.x, xa.y, xa.z, xa.w};
                const uint32_t ub[4] = {xb.x, xb.y, xb.z, xb.w};
                #pragma unroll
                for (int bp = 0; bp < 4; bp++) {
                    x2a[bp] = pack2(ua[bp] << 16, ua[bp] & 0xffff0000u);
                    x2b[bp] = pack2(ub[bp] << 16, ub[bp] & 0xffff0000u);
                }
            }
            #pragma unroll
            for (int n = 0; n < NOUT; n++) {
                const int qa = jp ? qv[n].z : qv[n].x;
                const int qb = jp ? qv[n].w : qv[n].y;
                // exact (q-8)*s in f32, RN->bf16 (ref bf16 mul), bf16 add of zero
                const float ta = fmaf((float)qa, s[n], m8s[n]);
                const float tb = fmaf((float)qb, s[n], m8s[n]);
                const __nv_bfloat162 w2 = __hadd2(__floats2bfloat162_rn(ta, tb), z2[n]);
                const uint32_t w2u = *reinterpret_cast<const uint32_t*>(&w2);
                const uint32_t wau = w2u << 16;
                const uint32_t wbu = w2u & 0xffff0000u;
                const ull wa2 = pack2(wau, wau);
                const ull wb2 = pack2(wbu, wbu);
                #pragma unroll
                for (int bp = 0; bp < 4; bp++) {
                    acc[n][bp] = ffma2(wa2, x2a[bp], acc[n][bp]);
                    acc[n][bp] = ffma2(wb2, x2b[bp], acc[n][bp]);
                }
            }
        }

        #pragma unroll
        for (int n = 0; n < NOUT; n++) qv[n] = qn[n];
    }

    // unpack and warp-reduce
    float r[NOUT][BATCH];
    #pragma unroll
    for (int n = 0; n < NOUT; n++)
        #pragma unroll
        for (int bp = 0; bp < 4; bp++)
            unpack2(acc[n][bp], r[n][2 * bp], r[n][2 * bp + 1]);

    #pragma unroll
    for (int m = 16; m >= 1; m >>= 1)
        #pragma unroll
        for (int n = 0; n < NOUT; n++)
            #pragma unroll
            for (int b = 0; b < BATCH; b++)
                r[n][b] += __shfl_xor_sync(0xffffffffu, r[n][b], m);

    // epilogue: lane b stores batch b; bf16-round (ref output is bf16-valued)
    #pragma unroll
    for (int b = 0; b < BATCH; b++) {
        if (lane == b) {
            #pragma unroll
            for (int n = 0; n < NOUT; n++)
                out[(size_t)b * OUTF + o0 + n] = bf16_rn(r[n][b]);
        }
    }
}

extern "C" void kernel_launch(void* const* d_in, const int* in_sizes, int n_in,
                              void* d_out, int out_size)
{
    // Route inputs by element count (order-proof); fall back to positional.
    const float*  x  = nullptr;   // 8*4096      = 32768
    const int*    qw = nullptr;   // 11008*4096  = 45088768
    const float2* sz = nullptr;   // 32*11008*2  = 704512 scalars
    for (int i = 0; i < n_in; i++) {
        if      (in_sizes[i] == BATCH * INF)         x  = (const float*)d_in[i];
        else if (in_sizes[i] == OUTF * INF)          qw = (const int*)d_in[i];
        else if (in_sizes[i] == NGROUPS * OUTF * 2)  sz = (const float2*)d_in[i];
    }
    if (!x || !qw || !sz) {
        x  = (const float*)d_in[0];
        qw = (const int*)d_in[1];
        sz = (const float2*)d_in[2];
    }
    float* out = (float*)d_out;

    xt_kernel<<<INF / 256, 256>>>(x);
    wo4l_kernel<<<GRID, THREADS>>>(qw, sz, out);
}